// round 6
// baseline (speedup 1.0000x reference)
#include <cuda_runtime.h>
#include <math.h>
#include <stdint.h>

// Problem dims (fixed)
#define BB   128
#define TT   1024
#define DD   512
#define HH   512
#define H3   1536
#define NCLS 2

typedef unsigned long long ull;

// ---------------- scratch ---------------------------------------------------
__device__ float  g_xp[(size_t)BB * TT * H3];   // [B*T, 3H], row m = b*T + t
__device__ float2 g_Rp[768 * 512];              // paired Rt: g_Rp[i][k] = (R[k][2i], R[k][2i+1])
__device__ float  g_hT[2][HH * BB];             // hidden, TRANSPOSED [k][r]
__device__ unsigned int g_bar;

// ---------------- f32x2 helpers ---------------------------------------------
__device__ __forceinline__ ull pack2(float a, float b) {
    ull r; asm("mov.b64 %0, {%1, %2};" : "=l"(r) : "f"(a), "f"(b)); return r;
}
__device__ __forceinline__ void unpack2(ull p, float& a, float& b) {
    asm("mov.b64 {%0, %1}, %2;" : "=f"(a), "=f"(b) : "l"(p));
}
__device__ __forceinline__ ull ffma2(ull a, ull b, ull c) {
    ull d; asm("fma.rn.f32x2 %0, %1, %2, %3;" : "=l"(d) : "l"(a), "l"(b), "l"(c)); return d;
}
__device__ __forceinline__ void cpa16(uint32_t s, const void* g) {
    asm volatile("cp.async.cg.shared.global [%0], [%1], 16;" :: "r"(s), "l"(g));
}
#define CP_COMMIT() asm volatile("cp.async.commit_group;")
#define CP_WAIT0()  asm volatile("cp.async.wait_group 0;")

// ---------------- init -------------------------------------------------------
__global__ void init_kernel() {
    int idx = blockIdx.x * blockDim.x + threadIdx.x;
    if (idx == 0) g_bar = 0u;
    if (idx < BB * HH) g_hT[0][idx] = 0.0f;
}

// ---------------- build paired R: R [H,3H] -> g_Rp [768][512] ----------------
__global__ void build_Rp(const float* __restrict__ R) {
    int idx = blockIdx.x * blockDim.x + threadIdx.x;  // over 768*512
    if (idx < 768 * 512) {
        int i = idx >> 9;        // pair index (0..767), cols 2i,2i+1
        int k = idx & 511;
        g_Rp[idx] = make_float2(R[(size_t)k * H3 + 2 * i], R[(size_t)k * H3 + 2 * i + 1]);
    }
}

// ---------------- GEMM1: xp = x @ W + b_i (f32x2) ----------------------------
#define BM 128
#define BN 128
#define BKK 8
#define TM 8
#define TN 8

__global__ void __launch_bounds__(256, 2)
gemm_xw(const float* __restrict__ A, const float* __restrict__ Bm,
        const float* __restrict__ bias, float* __restrict__ C,
        int M, int N, int K) {
    __shared__ float As[BKK][BM];
    __shared__ float Bs[BKK][BN];

    const int tid = threadIdx.x;
    const int brow = blockIdx.y;
    const int bcol = blockIdx.x;

    const int a_row = tid >> 1;
    const int a_col = (tid & 1) * 4;
    const int b_row = tid >> 5;
    const int b_col = (tid & 31) * 4;

    const int tx = tid & 15;
    const int ty = tid >> 4;

    ull accp[TM][TN / 2];
#pragma unroll
    for (int i = 0; i < TM; ++i)
#pragma unroll
        for (int j = 0; j < TN / 2; ++j) accp[i][j] = 0ull;

    const float* Ab = A + (size_t)(brow * BM) * K;
    const float* Bb = Bm + bcol * BN;

    for (int k0 = 0; k0 < K; k0 += BKK) {
        float4 av = *(const float4*)(Ab + (size_t)a_row * K + k0 + a_col);
        As[a_col + 0][a_row] = av.x;
        As[a_col + 1][a_row] = av.y;
        As[a_col + 2][a_row] = av.z;
        As[a_col + 3][a_row] = av.w;
        float4 bv = *(const float4*)(Bb + (size_t)(k0 + b_row) * N + b_col);
        *(float4*)&Bs[b_row][b_col] = bv;
        __syncthreads();

#pragma unroll
        for (int k = 0; k < BKK; ++k) {
            float ar[TM];
            float4 a0 = *(const float4*)&As[k][ty * TM];
            float4 a1 = *(const float4*)&As[k][ty * TM + 4];
            ar[0]=a0.x; ar[1]=a0.y; ar[2]=a0.z; ar[3]=a0.w;
            ar[4]=a1.x; ar[5]=a1.y; ar[6]=a1.z; ar[7]=a1.w;
            ulonglong2 bq0 = *(const ulonglong2*)&Bs[k][tx * TN];
            ulonglong2 bq1 = *(const ulonglong2*)&Bs[k][tx * TN + 4];
            ull bp0 = bq0.x, bp1 = bq0.y, bp2 = bq1.x, bp3 = bq1.y;
#pragma unroll
            for (int i = 0; i < TM; ++i) {
                ull as = pack2(ar[i], ar[i]);
                accp[i][0] = ffma2(as, bp0, accp[i][0]);
                accp[i][1] = ffma2(as, bp1, accp[i][1]);
                accp[i][2] = ffma2(as, bp2, accp[i][2]);
                accp[i][3] = ffma2(as, bp3, accp[i][3]);
            }
        }
        __syncthreads();
    }

    const int c_col0 = bcol * BN + tx * TN;
    float bsv[TN];
#pragma unroll
    for (int j = 0; j < TN; ++j) bsv[j] = bias[c_col0 + j];

    float* Cb = C + (size_t)(brow * BM + ty * TM) * N + c_col0;
#pragma unroll
    for (int i = 0; i < TM; ++i) {
#pragma unroll
        for (int j = 0; j < TN / 2; ++j) {
            float lo, hi; unpack2(accp[i][j], lo, hi);
            Cb[(size_t)i * N + 2 * j]     = lo + bsv[2 * j];
            Cb[(size_t)i * N + 2 * j + 1] = hi + bsv[2 * j + 1];
        }
    }
}

// ---------------- persistent GRU recurrence (v2) -----------------------------
// 128 CTAs x 128 threads. CTA owns cols j0..j0+3.
// thread: cp = tid>>6 (colpair), rp = tid&63 (row pair, rows 2rp, 2rp+1).
// h stored transposed in global: g_hT[k*128 + r]. R pre-paired in g_Rp.
#define RK 64
#define NCHUNK (HH / RK)   // 8

__device__ __forceinline__ float fsig(float x) {
    return 1.0f / (1.0f + __expf(-x));
}
__device__ __forceinline__ float ftanh(float x) {
    return 1.0f - 2.0f / (__expf(2.0f * x) + 1.0f);
}

__global__ void __launch_bounds__(128, 1)
gru_recurrent(const float* __restrict__ xp, const float* __restrict__ brv) {
    extern __shared__ char smem_raw[];
    float*  hs = (float*)smem_raw;                        // 2 bufs x RK x BB = 64KB
    float2* Rs = (float2*)(smem_raw + 2 * RK * BB * 4);   // 6 x 512 float2 = 24KB

    const int tid = threadIdx.x;
    const int cpi = tid >> 6;          // 0..1
    const int rp  = tid & 63;          // 0..63
    const int r0  = rp * 2;
    const int j0  = blockIdx.x * 4;
    const int c0  = j0 + 2 * cpi;

    // load persistent paired R rows: local row L = g*2+cp -> pair g*256 + c0/2
    for (int i = tid; i < 6 * 512; i += 128) {
        int L = i >> 9;
        int k = i & 511;
        int g = L >> 1, cc = L & 1;
        int gp = g * 256 + (j0 >> 1) + cc;
        Rs[(size_t)L * 512 + k] = g_Rp[(size_t)gp * 512 + k];
    }

    // biases for this thread's column pair (c0, c0+1)
    const float2 bz2 = *(const float2*)(brv + c0);
    const float2 br2 = *(const float2*)(brv + HH + c0);
    const float2 bh2 = *(const float2*)(brv + 2 * HH + c0);

    const unsigned nCTA = gridDim.x;
    uint32_t hs_s = (uint32_t)__cvta_generic_to_shared(hs);

    for (int t = 0; t < TT; ++t) {
        const float* hcur = g_hT[t & 1];
        float* hnx = g_hT[(t + 1) & 1];

        // prefetch chunk 0 into buffer 0
        {
            uint32_t dst = hs_s + tid * 256;
            const char* src = (const char*)hcur + tid * 256;
#pragma unroll
            for (int j = 0; j < 16; ++j) cpa16(dst + j * 16, src + j * 16);
            CP_COMMIT();
        }

        ull az0 = 0, az1 = 0, ar0 = 0, ar1 = 0, ah0 = 0, ah1 = 0;

        for (int c = 0; c < NCHUNK; ++c) {
            CP_WAIT0();
            __syncthreads();
            if (c < NCHUNK - 1) {
                uint32_t dst = hs_s + ((c + 1) & 1) * (RK * BB * 4) + tid * 256;
                const char* src = (const char*)(hcur + (c + 1) * RK * BB) + tid * 256;
#pragma unroll
                for (int j = 0; j < 16; ++j) cpa16(dst + j * 16, src + j * 16);
                CP_COMMIT();
            }
            const float* hb = hs + (c & 1) * (RK * BB);
            const float2* Rz = Rs + (size_t)(0 + cpi) * 512 + c * RK;
            const float2* Rr = Rs + (size_t)(2 + cpi) * 512 + c * RK;
            const float2* Rh = Rs + (size_t)(4 + cpi) * 512 + c * RK;

#pragma unroll 8
            for (int k = 0; k < RK; k += 2) {
                ull hp0 = *(const ull*)(hb + (size_t)k * BB + r0);
                ull hp1 = *(const ull*)(hb + (size_t)(k + 1) * BB + r0);
                float h00, h01; unpack2(hp0, h00, h01);
                float h10, h11; unpack2(hp1, h10, h11);
                ull s00 = pack2(h00, h00), s01 = pack2(h01, h01);
                ull s10 = pack2(h10, h10), s11 = pack2(h11, h11);

                ulonglong2 vz = *(const ulonglong2*)(Rz + k);
                ulonglong2 vr = *(const ulonglong2*)(Rr + k);
                ulonglong2 vh = *(const ulonglong2*)(Rh + k);

                az0 = ffma2(s00, vz.x, az0);  az1 = ffma2(s01, vz.x, az1);
                ar0 = ffma2(s00, vr.x, ar0);  ar1 = ffma2(s01, vr.x, ar1);
                ah0 = ffma2(s00, vh.x, ah0);  ah1 = ffma2(s01, vh.x, ah1);
                az0 = ffma2(s10, vz.y, az0);  az1 = ffma2(s11, vz.y, az1);
                ar0 = ffma2(s10, vr.y, ar0);  ar1 = ffma2(s11, vr.y, ar1);
                ah0 = ffma2(s10, vh.y, ah0);  ah1 = ffma2(s11, vh.y, ah1);
            }
        }

        // gate math for (rows r0,r0+1) x (cols c0,c0+1)
        float azc[2][2], arc[2][2], ahc[2][2];
        unpack2(az0, azc[0][0], azc[0][1]);
        unpack2(az1, azc[1][0], azc[1][1]);
        unpack2(ar0, arc[0][0], arc[0][1]);
        unpack2(ar1, arc[1][0], arc[1][1]);
        unpack2(ah0, ahc[0][0], ahc[0][1]);
        unpack2(ah1, ahc[1][0], ahc[1][1]);

        float2 ho0 = *(const float2*)(hcur + (size_t)c0 * BB + r0);        // (r0,r1) @ c0
        float2 ho1 = *(const float2*)(hcur + (size_t)(c0 + 1) * BB + r0);  // (r0,r1) @ c1
        float hold[2][2] = {{ho0.x, ho1.x}, {ho0.y, ho1.y}};

        float hnew[2][2];
#pragma unroll
        for (int rr = 0; rr < 2; ++rr) {
            const float* xb = xp + ((size_t)(r0 + rr) * TT + t) * H3;
            float2 xz2 = *(const float2*)(xb + c0);
            float2 xr2 = *(const float2*)(xb + HH + c0);
            float2 xh2 = *(const float2*)(xb + 2 * HH + c0);
            float xzv[2] = {xz2.x, xz2.y};
            float xrv[2] = {xr2.x, xr2.y};
            float xhv[2] = {xh2.x, xh2.y};
            float bzv[2] = {bz2.x, bz2.y};
            float brvv[2] = {br2.x, br2.y};
            float bhv[2] = {bh2.x, bh2.y};
#pragma unroll
            for (int cc = 0; cc < 2; ++cc) {
                float z  = fsig(xzv[cc] + azc[rr][cc] + bzv[cc]);
                float rg = fsig(xrv[cc] + arc[rr][cc] + brvv[cc]);
                float hh = ftanh(xhv[cc] + rg * (ahc[rr][cc] + bhv[cc]));
                hnew[rr][cc] = z * hold[rr][cc] + (1.0f - z) * hh;
            }
        }
        *(float2*)(hnx + (size_t)c0 * BB + r0)       = make_float2(hnew[0][0], hnew[1][0]);
        *(float2*)(hnx + (size_t)(c0 + 1) * BB + r0) = make_float2(hnew[0][1], hnew[1][1]);

        // grid barrier
        __threadfence();
        __syncthreads();
        if (tid == 0) {
            atomicAdd(&g_bar, 1u);
            unsigned target = nCTA * (unsigned)(t + 1);
            while (*(volatile unsigned*)&g_bar < target) { }
            __threadfence();
        }
        __syncthreads();
    }
}

// ---------------- final: logits = h_last @ Wf + bf ---------------------------
__global__ void final_logits(const float* __restrict__ Wf,
                             const float* __restrict__ bf,
                             float* __restrict__ out) {
    int tid = threadIdx.x;          // 256 threads: r = tid>>1, c = tid&1
    int r = tid >> 1;
    int c = tid & 1;
    const float* h = g_hT[TT & 1];  // T even -> buffer 0, layout [k][r]
    float acc = 0.0f;
    for (int k = 0; k < HH; ++k)
        acc += h[(size_t)k * BB + r] * Wf[k * NCLS + c];
    out[r * NCLS + c] = acc + bf[c];
}

// ---------------- launch -----------------------------------------------------
extern "C" void kernel_launch(void* const* d_in, const int* in_sizes, int n_in,
                              void* d_out, int out_size) {
    const float* x   = (const float*)d_in[0];
    const float* W   = (const float*)d_in[1];
    const float* R   = (const float*)d_in[2];
    const float* b_i = (const float*)d_in[3];
    const float* b_r = (const float*)d_in[4];
    const float* Wf  = (const float*)d_in[5];
    const float* bf  = (const float*)d_in[6];
    float* out = (float*)d_out;

    float* xp;
    cudaGetSymbolAddress((void**)&xp, g_xp);

    static bool attr_set = false;
    if (!attr_set) {
        cudaFuncSetAttribute(gru_recurrent,
                             cudaFuncAttributeMaxDynamicSharedMemorySize,
                             2 * RK * BB * 4 + 6 * 512 * 8);
        attr_set = true;
    }

    init_kernel<<<(BB * HH + 255) / 256, 256>>>();
    build_Rp<<<(768 * 512 + 255) / 256, 256>>>(R);
    {
        dim3 grid(H3 / BN, (BB * TT) / BM);
        gemm_xw<<<grid, 256>>>(x, W, b_i, xp, BB * TT, H3, DD);
    }
    gru_recurrent<<<HH / 4, 128, 2 * RK * BB * 4 + 6 * 512 * 8>>>(xp, b_r);
    final_logits<<<1, 256>>>(Wf, bf, out);
}

// round 7
// speedup vs baseline: 1.0076x; 1.0076x over previous
#include <cuda_runtime.h>
#include <math.h>
#include <stdint.h>

// Problem dims (fixed)
#define BB   128
#define TT   1024
#define DD   512
#define HH   512
#define H3   1536
#define NCLS 2

typedef unsigned long long ull;

// ---------------- scratch ---------------------------------------------------
__device__ float  g_xp[(size_t)BB * TT * H3];   // [B*T, 3H], row m = b*T + t
__device__ float2 g_Rp[768 * 512];              // paired Rt: g_Rp[i][k] = (R[k][2i], R[k][2i+1])
__device__ float  g_hT[2][HH * BB];             // hidden, TRANSPOSED [k][r]
__device__ unsigned int g_bar;

// ---------------- f32x2 helpers ---------------------------------------------
__device__ __forceinline__ ull pack2(float a, float b) {
    ull r; asm("mov.b64 %0, {%1, %2};" : "=l"(r) : "f"(a), "f"(b)); return r;
}
__device__ __forceinline__ void unpack2(ull p, float& a, float& b) {
    asm("mov.b64 {%0, %1}, %2;" : "=f"(a), "=f"(b) : "l"(p));
}
__device__ __forceinline__ ull ffma2(ull a, ull b, ull c) {
    ull d; asm("fma.rn.f32x2 %0, %1, %2, %3;" : "=l"(d) : "l"(a), "l"(b), "l"(c)); return d;
}
__device__ __forceinline__ void cpa16(uint32_t s, const void* g) {
    asm volatile("cp.async.cg.shared.global [%0], [%1], 16;" :: "r"(s), "l"(g));
}
#define CP_COMMIT() asm volatile("cp.async.commit_group;")
#define CP_WAIT0()  asm volatile("cp.async.wait_group 0;")

// ---------------- init -------------------------------------------------------
__global__ void init_kernel() {
    int idx = blockIdx.x * blockDim.x + threadIdx.x;
    if (idx == 0) g_bar = 0u;
    if (idx < BB * HH) g_hT[0][idx] = 0.0f;
}

// ---------------- build paired R: R [H,3H] -> g_Rp [768][512] ----------------
__global__ void build_Rp(const float* __restrict__ R) {
    int idx = blockIdx.x * blockDim.x + threadIdx.x;  // over 768*512
    if (idx < 768 * 512) {
        int i = idx >> 9;        // pair index (0..767), cols 2i,2i+1
        int k = idx & 511;
        g_Rp[idx] = make_float2(R[(size_t)k * H3 + 2 * i], R[(size_t)k * H3 + 2 * i + 1]);
    }
}

// ---------------- GEMM1: xp = x @ W + b_i (f32x2) ----------------------------
#define BM 128
#define BN 128
#define BKK 8
#define TM 8
#define TN 8

__global__ void __launch_bounds__(256, 2)
gemm_xw(const float* __restrict__ A, const float* __restrict__ Bm,
        const float* __restrict__ bias, float* __restrict__ C,
        int M, int N, int K) {
    __shared__ float As[BKK][BM];
    __shared__ float Bs[BKK][BN];

    const int tid = threadIdx.x;
    const int brow = blockIdx.y;
    const int bcol = blockIdx.x;

    const int a_row = tid >> 1;
    const int a_col = (tid & 1) * 4;
    const int b_row = tid >> 5;
    const int b_col = (tid & 31) * 4;

    const int tx = tid & 15;
    const int ty = tid >> 4;

    ull accp[TM][TN / 2];
#pragma unroll
    for (int i = 0; i < TM; ++i)
#pragma unroll
        for (int j = 0; j < TN / 2; ++j) accp[i][j] = 0ull;

    const float* Ab = A + (size_t)(brow * BM) * K;
    const float* Bb = Bm + bcol * BN;

    for (int k0 = 0; k0 < K; k0 += BKK) {
        float4 av = *(const float4*)(Ab + (size_t)a_row * K + k0 + a_col);
        As[a_col + 0][a_row] = av.x;
        As[a_col + 1][a_row] = av.y;
        As[a_col + 2][a_row] = av.z;
        As[a_col + 3][a_row] = av.w;
        float4 bv = *(const float4*)(Bb + (size_t)(k0 + b_row) * N + b_col);
        *(float4*)&Bs[b_row][b_col] = bv;
        __syncthreads();

#pragma unroll
        for (int k = 0; k < BKK; ++k) {
            float ar[TM];
            float4 a0 = *(const float4*)&As[k][ty * TM];
            float4 a1 = *(const float4*)&As[k][ty * TM + 4];
            ar[0]=a0.x; ar[1]=a0.y; ar[2]=a0.z; ar[3]=a0.w;
            ar[4]=a1.x; ar[5]=a1.y; ar[6]=a1.z; ar[7]=a1.w;
            ulonglong2 bq0 = *(const ulonglong2*)&Bs[k][tx * TN];
            ulonglong2 bq1 = *(const ulonglong2*)&Bs[k][tx * TN + 4];
            ull bp0 = bq0.x, bp1 = bq0.y, bp2 = bq1.x, bp3 = bq1.y;
#pragma unroll
            for (int i = 0; i < TM; ++i) {
                ull as = pack2(ar[i], ar[i]);
                accp[i][0] = ffma2(as, bp0, accp[i][0]);
                accp[i][1] = ffma2(as, bp1, accp[i][1]);
                accp[i][2] = ffma2(as, bp2, accp[i][2]);
                accp[i][3] = ffma2(as, bp3, accp[i][3]);
            }
        }
        __syncthreads();
    }

    const int c_col0 = bcol * BN + tx * TN;
    float bsv[TN];
#pragma unroll
    for (int j = 0; j < TN; ++j) bsv[j] = bias[c_col0 + j];

    float* Cb = C + (size_t)(brow * BM + ty * TM) * N + c_col0;
#pragma unroll
    for (int i = 0; i < TM; ++i) {
#pragma unroll
        for (int j = 0; j < TN / 2; ++j) {
            float lo, hi; unpack2(accp[i][j], lo, hi);
            Cb[(size_t)i * N + 2 * j]     = lo + bsv[2 * j];
            Cb[(size_t)i * N + 2 * j + 1] = hi + bsv[2 * j + 1];
        }
    }
}

// ---------------- persistent GRU recurrence (v2) -----------------------------
// 128 CTAs x 128 threads. CTA owns cols j0..j0+3.
// thread: cp = tid>>6 (colpair), rp = tid&63 (row pair, rows 2rp, 2rp+1).
// h stored transposed in global: g_hT[k*128 + r]. R pre-paired in g_Rp.
#define RK 64
#define NCHUNK (HH / RK)   // 8

__device__ __forceinline__ float fsig(float x) {
    return 1.0f / (1.0f + __expf(-x));
}
__device__ __forceinline__ float ftanh(float x) {
    return 1.0f - 2.0f / (__expf(2.0f * x) + 1.0f);
}

__global__ void __launch_bounds__(128, 1)
gru_recurrent(const float* __restrict__ xp, const float* __restrict__ brv) {
    extern __shared__ char smem_raw[];
    float*  hs = (float*)smem_raw;                        // 2 bufs x RK x BB = 64KB
    float2* Rs = (float2*)(smem_raw + 2 * RK * BB * 4);   // 6 x 512 float2 = 24KB

    const int tid = threadIdx.x;
    const int cpi = tid >> 6;          // 0..1
    const int rp  = tid & 63;          // 0..63
    const int r0  = rp * 2;
    const int j0  = blockIdx.x * 4;
    const int c0  = j0 + 2 * cpi;

    // load persistent paired R rows: local row L = g*2+cp -> pair g*256 + c0/2
    for (int i = tid; i < 6 * 512; i += 128) {
        int L = i >> 9;
        int k = i & 511;
        int g = L >> 1, cc = L & 1;
        int gp = g * 256 + (j0 >> 1) + cc;
        Rs[(size_t)L * 512 + k] = g_Rp[(size_t)gp * 512 + k];
    }

    // biases for this thread's column pair (c0, c0+1)
    const float2 bz2 = *(const float2*)(brv + c0);
    const float2 br2 = *(const float2*)(brv + HH + c0);
    const float2 bh2 = *(const float2*)(brv + 2 * HH + c0);

    const unsigned nCTA = gridDim.x;
    uint32_t hs_s = (uint32_t)__cvta_generic_to_shared(hs);

    for (int t = 0; t < TT; ++t) {
        const float* hcur = g_hT[t & 1];
        float* hnx = g_hT[(t + 1) & 1];

        // prefetch chunk 0 into buffer 0
        {
            uint32_t dst = hs_s + tid * 256;
            const char* src = (const char*)hcur + tid * 256;
#pragma unroll
            for (int j = 0; j < 16; ++j) cpa16(dst + j * 16, src + j * 16);
            CP_COMMIT();
        }

        ull az0 = 0, az1 = 0, ar0 = 0, ar1 = 0, ah0 = 0, ah1 = 0;

        for (int c = 0; c < NCHUNK; ++c) {
            CP_WAIT0();
            __syncthreads();
            if (c < NCHUNK - 1) {
                uint32_t dst = hs_s + ((c + 1) & 1) * (RK * BB * 4) + tid * 256;
                const char* src = (const char*)(hcur + (c + 1) * RK * BB) + tid * 256;
#pragma unroll
                for (int j = 0; j < 16; ++j) cpa16(dst + j * 16, src + j * 16);
                CP_COMMIT();
            }
            const float* hb = hs + (c & 1) * (RK * BB);
            const float2* Rz = Rs + (size_t)(0 + cpi) * 512 + c * RK;
            const float2* Rr = Rs + (size_t)(2 + cpi) * 512 + c * RK;
            const float2* Rh = Rs + (size_t)(4 + cpi) * 512 + c * RK;

#pragma unroll 8
            for (int k = 0; k < RK; k += 2) {
                ull hp0 = *(const ull*)(hb + (size_t)k * BB + r0);
                ull hp1 = *(const ull*)(hb + (size_t)(k + 1) * BB + r0);
                float h00, h01; unpack2(hp0, h00, h01);
                float h10, h11; unpack2(hp1, h10, h11);
                ull s00 = pack2(h00, h00), s01 = pack2(h01, h01);
                ull s10 = pack2(h10, h10), s11 = pack2(h11, h11);

                ulonglong2 vz = *(const ulonglong2*)(Rz + k);
                ulonglong2 vr = *(const ulonglong2*)(Rr + k);
                ulonglong2 vh = *(const ulonglong2*)(Rh + k);

                az0 = ffma2(s00, vz.x, az0);  az1 = ffma2(s01, vz.x, az1);
                ar0 = ffma2(s00, vr.x, ar0);  ar1 = ffma2(s01, vr.x, ar1);
                ah0 = ffma2(s00, vh.x, ah0);  ah1 = ffma2(s01, vh.x, ah1);
                az0 = ffma2(s10, vz.y, az0);  az1 = ffma2(s11, vz.y, az1);
                ar0 = ffma2(s10, vr.y, ar0);  ar1 = ffma2(s11, vr.y, ar1);
                ah0 = ffma2(s10, vh.y, ah0);  ah1 = ffma2(s11, vh.y, ah1);
            }
        }

        // gate math for (rows r0,r0+1) x (cols c0,c0+1)
        float azc[2][2], arc[2][2], ahc[2][2];
        unpack2(az0, azc[0][0], azc[0][1]);
        unpack2(az1, azc[1][0], azc[1][1]);
        unpack2(ar0, arc[0][0], arc[0][1]);
        unpack2(ar1, arc[1][0], arc[1][1]);
        unpack2(ah0, ahc[0][0], ahc[0][1]);
        unpack2(ah1, ahc[1][0], ahc[1][1]);

        float2 ho0 = *(const float2*)(hcur + (size_t)c0 * BB + r0);        // (r0,r1) @ c0
        float2 ho1 = *(const float2*)(hcur + (size_t)(c0 + 1) * BB + r0);  // (r0,r1) @ c1
        float hold[2][2] = {{ho0.x, ho1.x}, {ho0.y, ho1.y}};

        float hnew[2][2];
#pragma unroll
        for (int rr = 0; rr < 2; ++rr) {
            const float* xb = xp + ((size_t)(r0 + rr) * TT + t) * H3;
            float2 xz2 = *(const float2*)(xb + c0);
            float2 xr2 = *(const float2*)(xb + HH + c0);
            float2 xh2 = *(const float2*)(xb + 2 * HH + c0);
            float xzv[2] = {xz2.x, xz2.y};
            float xrv[2] = {xr2.x, xr2.y};
            float xhv[2] = {xh2.x, xh2.y};
            float bzv[2] = {bz2.x, bz2.y};
            float brvv[2] = {br2.x, br2.y};
            float bhv[2] = {bh2.x, bh2.y};
#pragma unroll
            for (int cc = 0; cc < 2; ++cc) {
                float z  = fsig(xzv[cc] + azc[rr][cc] + bzv[cc]);
                float rg = fsig(xrv[cc] + arc[rr][cc] + brvv[cc]);
                float hh = ftanh(xhv[cc] + rg * (ahc[rr][cc] + bhv[cc]));
                hnew[rr][cc] = z * hold[rr][cc] + (1.0f - z) * hh;
            }
        }
        *(float2*)(hnx + (size_t)c0 * BB + r0)       = make_float2(hnew[0][0], hnew[1][0]);
        *(float2*)(hnx + (size_t)(c0 + 1) * BB + r0) = make_float2(hnew[0][1], hnew[1][1]);

        // grid barrier
        __threadfence();
        __syncthreads();
        if (tid == 0) {
            atomicAdd(&g_bar, 1u);
            unsigned target = nCTA * (unsigned)(t + 1);
            while (*(volatile unsigned*)&g_bar < target) { }
            __threadfence();
        }
        __syncthreads();
    }
}

// ---------------- final: logits = h_last @ Wf + bf ---------------------------
__global__ void final_logits(const float* __restrict__ Wf,
                             const float* __restrict__ bf,
                             float* __restrict__ out) {
    int tid = threadIdx.x;          // 256 threads: r = tid>>1, c = tid&1
    int r = tid >> 1;
    int c = tid & 1;
    const float* h = g_hT[TT & 1];  // T even -> buffer 0, layout [k][r]
    float acc = 0.0f;
    for (int k = 0; k < HH; ++k)
        acc += h[(size_t)k * BB + r] * Wf[k * NCLS + c];
    out[r * NCLS + c] = acc + bf[c];
}

// ---------------- launch -----------------------------------------------------
extern "C" void kernel_launch(void* const* d_in, const int* in_sizes, int n_in,
                              void* d_out, int out_size) {
    const float* x   = (const float*)d_in[0];
    const float* W   = (const float*)d_in[1];
    const float* R   = (const float*)d_in[2];
    const float* b_i = (const float*)d_in[3];
    const float* b_r = (const float*)d_in[4];
    const float* Wf  = (const float*)d_in[5];
    const float* bf  = (const float*)d_in[6];
    float* out = (float*)d_out;

    float* xp;
    cudaGetSymbolAddress((void**)&xp, g_xp);

    static bool attr_set = false;
    if (!attr_set) {
        cudaFuncSetAttribute(gru_recurrent,
                             cudaFuncAttributeMaxDynamicSharedMemorySize,
                             2 * RK * BB * 4 + 6 * 512 * 8);
        attr_set = true;
    }

    init_kernel<<<(BB * HH + 255) / 256, 256>>>();
    build_Rp<<<(768 * 512 + 255) / 256, 256>>>(R);
    {
        dim3 grid(H3 / BN, (BB * TT) / BM);
        gemm_xw<<<grid, 256>>>(x, W, b_i, xp, BB * TT, H3, DD);
    }
    gru_recurrent<<<HH / 4, 128, 2 * RK * BB * 4 + 6 * 512 * 8>>>(xp, b_r);
    final_logits<<<1, 256>>>(Wf, bf, out);
}

// round 10
// speedup vs baseline: 1.0258x; 1.0180x over previous
#include <cuda_runtime.h>
#include <math.h>
#include <stdint.h>

// Problem dims (fixed)
#define BB   128
#define TT   1024
#define DD   512
#define HH   512
#define H3   1536
#define NCLS 2

typedef unsigned long long ull;

// recurrence smem layout
#define RK 64
#define CHUNK_B (RK * BB * 4)        // 32768 bytes per 64-k chunk
#define HS_TOT  (4 * CHUNK_B)        // 2 stages x 2 halves = 128KB
#define RS_OFF  HS_TOT
#define RS_B    (6 * 512 * 8)        // 24KB persistent paired R
#define RED_OFF (RS_OFF + RS_B)
#define RED_B   (128 * 6 * 8)        // 6KB reduction buffer
#define SMEM_DYN (RED_OFF + RED_B + 64)

// ---------------- scratch ----------------------------------------------------
__device__ float  g_xp[(size_t)BB * TT * H3];   // [B*T, 3H], row m = b*T + t
__device__ float2 g_Rp[768 * 512];              // paired Rt: g_Rp[i][k] = (R[k][2i], R[k][2i+1])
__device__ float  g_hT[2][HH * BB];             // hidden, TRANSPOSED [k][r]
__device__ unsigned int g_bar;

// ---------------- f32x2 helpers ---------------------------------------------
__device__ __forceinline__ ull pack2(float a, float b) {
    ull r; asm("mov.b64 %0, {%1, %2};" : "=l"(r) : "f"(a), "f"(b)); return r;
}
__device__ __forceinline__ void unpack2(ull p, float& a, float& b) {
    asm("mov.b64 {%0, %1}, %2;" : "=f"(a), "=f"(b) : "l"(p));
}
__device__ __forceinline__ ull ffma2(ull a, ull b, ull c) {
    ull d; asm("fma.rn.f32x2 %0, %1, %2, %3;" : "=l"(d) : "l"(a), "l"(b), "l"(c)); return d;
}
__device__ __forceinline__ ull addx2(ull a, ull b) {
    ull d; asm("add.rn.f32x2 %0, %1, %2;" : "=l"(d) : "l"(a), "l"(b)); return d;
}
__device__ __forceinline__ void cpa16(uint32_t s, const void* g) {
    asm volatile("cp.async.cg.shared.global [%0], [%1], 16;" :: "r"(s), "l"(g));
}
#define CP_COMMIT() asm volatile("cp.async.commit_group;")
#define CP_WAIT1()  asm volatile("cp.async.wait_group 1;")
#define CP_WAIT0()  asm volatile("cp.async.wait_group 0;")

// ---------------- init -------------------------------------------------------
__global__ void init_kernel() {
    int idx = blockIdx.x * blockDim.x + threadIdx.x;
    if (idx == 0) g_bar = 0u;
    if (idx < BB * HH) g_hT[0][idx] = 0.0f;
}

// ---------------- build paired R: R [H,3H] -> g_Rp [768][512] ----------------
__global__ void build_Rp(const float* __restrict__ R) {
    int idx = blockIdx.x * blockDim.x + threadIdx.x;  // over 768*512
    if (idx < 768 * 512) {
        int i = idx >> 9;        // pair index (0..767), cols 2i,2i+1
        int k = idx & 511;
        g_Rp[idx] = make_float2(R[(size_t)k * H3 + 2 * i], R[(size_t)k * H3 + 2 * i + 1]);
    }
}

// ---------------- GEMM1: xp = x @ W + b_i (f32x2) ----------------------------
#define BM 128
#define BN 128
#define BKK 8
#define TM 8
#define TN 8

__global__ void __launch_bounds__(256, 2)
gemm_xw(const float* __restrict__ A, const float* __restrict__ Bm,
        const float* __restrict__ bias, float* __restrict__ C,
        int M, int N, int K) {
    __shared__ float As[BKK][BM];
    __shared__ float Bs[BKK][BN];

    const int tid = threadIdx.x;
    const int brow = blockIdx.y;
    const int bcol = blockIdx.x;

    const int a_row = tid >> 1;
    const int a_col = (tid & 1) * 4;
    const int b_row = tid >> 5;
    const int b_col = (tid & 31) * 4;

    const int tx = tid & 15;
    const int ty = tid >> 4;

    ull accp[TM][TN / 2];
#pragma unroll
    for (int i = 0; i < TM; ++i)
#pragma unroll
        for (int j = 0; j < TN / 2; ++j) accp[i][j] = 0ull;

    const float* Ab = A + (size_t)(brow * BM) * K;
    const float* Bb = Bm + bcol * BN;

    for (int k0 = 0; k0 < K; k0 += BKK) {
        float4 av = *(const float4*)(Ab + (size_t)a_row * K + k0 + a_col);
        As[a_col + 0][a_row] = av.x;
        As[a_col + 1][a_row] = av.y;
        As[a_col + 2][a_row] = av.z;
        As[a_col + 3][a_row] = av.w;
        float4 bv = *(const float4*)(Bb + (size_t)(k0 + b_row) * N + b_col);
        *(float4*)&Bs[b_row][b_col] = bv;
        __syncthreads();

#pragma unroll
        for (int k = 0; k < BKK; ++k) {
            float ar[TM];
            float4 a0 = *(const float4*)&As[k][ty * TM];
            float4 a1 = *(const float4*)&As[k][ty * TM + 4];
            ar[0]=a0.x; ar[1]=a0.y; ar[2]=a0.z; ar[3]=a0.w;
            ar[4]=a1.x; ar[5]=a1.y; ar[6]=a1.z; ar[7]=a1.w;
            ulonglong2 bq0 = *(const ulonglong2*)&Bs[k][tx * TN];
            ulonglong2 bq1 = *(const ulonglong2*)&Bs[k][tx * TN + 4];
            ull bp0 = bq0.x, bp1 = bq0.y, bp2 = bq1.x, bp3 = bq1.y;
#pragma unroll
            for (int i = 0; i < TM; ++i) {
                ull as = pack2(ar[i], ar[i]);
                accp[i][0] = ffma2(as, bp0, accp[i][0]);
                accp[i][1] = ffma2(as, bp1, accp[i][1]);
                accp[i][2] = ffma2(as, bp2, accp[i][2]);
                accp[i][3] = ffma2(as, bp3, accp[i][3]);
            }
        }
        __syncthreads();
    }

    const int c_col0 = bcol * BN + tx * TN;
    float bsv[TN];
#pragma unroll
    for (int j = 0; j < TN; ++j) bsv[j] = bias[c_col0 + j];

    float* Cb = C + (size_t)(brow * BM + ty * TM) * N + c_col0;
#pragma unroll
    for (int i = 0; i < TM; ++i) {
#pragma unroll
        for (int j = 0; j < TN / 2; ++j) {
            float lo, hi; unpack2(accp[i][j], lo, hi);
            Cb[(size_t)i * N + 2 * j]     = lo + bsv[2 * j];
            Cb[(size_t)i * N + 2 * j + 1] = hi + bsv[2 * j + 1];
        }
    }
}

// ---------------- persistent GRU recurrence (v3b: K-split, 256 thr) ----------
// 128 CTAs x 256 threads. CTA owns cols j0..j0+3.
// half = tid>>7 reduces k in [half*256, half*256+256); lt = tid&127:
//   cpi = lt>>6 (colpair), rp = lt&63 (rows 2rp, 2rp+1).
// h transposed in global: g_hT[k*128 + r]. R pre-paired in g_Rp.
// h_old is read from GLOBAL in the prefetch phase (the staged smem copy gets
// overwritten by the pipeline before the epilogue — that was the R9 bug).

__device__ __forceinline__ float fsig(float x)  { return 1.0f / (1.0f + __expf(-x)); }
__device__ __forceinline__ float ftanh(float x) { return 1.0f - 2.0f / (__expf(2.0f * x) + 1.0f); }

// stage chunk pair (ci, ci+4) into regions (ci&1)*2 and (ci&1)*2+1; one commit
__device__ __forceinline__ void stage2(uint32_t hsS, const float* hcur, int ci, int tid) {
    uint32_t d0 = hsS + (uint32_t)(((ci & 1) << 1) * CHUNK_B) + tid * 128;
    const char* s0 = (const char*)hcur + (size_t)ci * CHUNK_B + tid * 128;
#pragma unroll
    for (int j = 0; j < 8; ++j) cpa16(d0 + j * 16, s0 + j * 16);
    uint32_t d1 = hsS + (uint32_t)((((ci & 1) << 1) | 1) * CHUNK_B) + tid * 128;
    const char* s1 = (const char*)hcur + (size_t)(4 + ci) * CHUNK_B + tid * 128;
#pragma unroll
    for (int j = 0; j < 8; ++j) cpa16(d1 + j * 16, s1 + j * 16);
    CP_COMMIT();
}

__global__ void __launch_bounds__(256, 1)
gru_recurrent(const float* __restrict__ xp, const float* __restrict__ brv) {
    extern __shared__ char sm[];
    float*  hs  = (float*)sm;
    float2* Rs  = (float2*)(sm + RS_OFF);
    ull*    red = (ull*)(sm + RED_OFF);

    const int tid  = threadIdx.x;
    const int half = tid >> 7;
    const int lt   = tid & 127;
    const int cpi  = lt >> 6;          // 0..1
    const int rp   = lt & 63;          // 0..63
    const int r0   = rp * 2;
    const int j0   = blockIdx.x * 4;
    const int c0   = j0 + 2 * cpi;

    // persistent paired R rows: L = gate*2 + colpair
    for (int i = tid; i < 6 * 512; i += 256) {
        int L = i >> 9;
        int k = i & 511;
        int g = L >> 1, cc = L & 1;
        int gp = g * 256 + (j0 >> 1) + cc;
        Rs[(size_t)L * 512 + k] = g_Rp[(size_t)gp * 512 + k];
    }

    const float2 bz2 = *(const float2*)(brv + c0);
    const float2 br2 = *(const float2*)(brv + HH + c0);
    const float2 bh2 = *(const float2*)(brv + 2 * HH + c0);

    const unsigned nCTA = gridDim.x;
    uint32_t hsS = (uint32_t)__cvta_generic_to_shared(hs);
    __syncthreads();

    for (int t = 0; t < TT; ++t) {
        const float* hcur = g_hT[t & 1];
        float* hnx = g_hT[(t + 1) & 1];

        // prefetch xp gate inputs AND h_old from global (latency overlaps MMA loop)
        float2 xzp[2], xrp[2], xhp[2];
        float2 ho0, ho1;
#pragma unroll
        for (int rr = 0; rr < 2; ++rr) {
            const float* xb = xp + ((size_t)(r0 + rr) * TT + t) * H3;
            xzp[rr] = *(const float2*)(xb + c0);
            xrp[rr] = *(const float2*)(xb + HH + c0);
            xhp[rr] = *(const float2*)(xb + 2 * HH + c0);
        }
        ho0 = *(const float2*)(hcur + (size_t)c0 * BB + r0);        // col c0,   rows r0,r0+1
        ho1 = *(const float2*)(hcur + (size_t)(c0 + 1) * BB + r0);  // col c0+1

        // prologue: stage chunk pairs 0 and 1
        stage2(hsS, hcur, 0, tid);
        stage2(hsS, hcur, 1, tid);

        ull az0 = 0, az1 = 0, ar0 = 0, ar1 = 0, ah0 = 0, ah1 = 0;

#pragma unroll
        for (int c = 0; c < 4; ++c) {
            if (c < 3) { CP_WAIT1(); } else { CP_WAIT0(); }
            __syncthreads();

            const float* hb = hs + (size_t)((((c & 1) << 1) | half) * (RK * BB));
            const int kg = half * 256 + c * RK;
            const float2* Rz = Rs + (size_t)(0 + cpi) * 512 + kg;
            const float2* Rr = Rs + (size_t)(2 + cpi) * 512 + kg;
            const float2* Rh = Rs + (size_t)(4 + cpi) * 512 + kg;

#pragma unroll 8
            for (int kk = 0; kk < RK; kk += 2) {
                ull hp0 = *(const ull*)(hb + (size_t)kk * BB + r0);
                ull hp1 = *(const ull*)(hb + (size_t)(kk + 1) * BB + r0);
                float h00, h01; unpack2(hp0, h00, h01);
                float h10, h11; unpack2(hp1, h10, h11);
                ull s00 = pack2(h00, h00), s01 = pack2(h01, h01);
                ull s10 = pack2(h10, h10), s11 = pack2(h11, h11);

                ulonglong2 vz = *(const ulonglong2*)(Rz + kk);
                ulonglong2 vr = *(const ulonglong2*)(Rr + kk);
                ulonglong2 vh = *(const ulonglong2*)(Rh + kk);

                az0 = ffma2(s00, vz.x, az0);  az1 = ffma2(s01, vz.x, az1);
                ar0 = ffma2(s00, vr.x, ar0);  ar1 = ffma2(s01, vr.x, ar1);
                ah0 = ffma2(s00, vh.x, ah0);  ah1 = ffma2(s01, vh.x, ah1);
                az0 = ffma2(s10, vz.y, az0);  az1 = ffma2(s11, vz.y, az1);
                ar0 = ffma2(s10, vr.y, ar0);  ar1 = ffma2(s11, vr.y, ar1);
                ah0 = ffma2(s10, vh.y, ah0);  ah1 = ffma2(s11, vh.y, ah1);
            }

            if (c < 2) {
                __syncthreads();           // all warps done with buffer (c&1)
                stage2(hsS, hcur, c + 2, tid);
            }
        }

        // K-split reduction: half 1 -> smem, half 0 accumulates
        if (half) {
            ull* rd = red + (size_t)lt * 6;
            rd[0] = az0; rd[1] = az1; rd[2] = ar0;
            rd[3] = ar1; rd[4] = ah0; rd[5] = ah1;
        }
        __syncthreads();
        if (!half) {
            const ull* rd = red + (size_t)lt * 6;
            az0 = addx2(az0, rd[0]); az1 = addx2(az1, rd[1]);
            ar0 = addx2(ar0, rd[2]); ar1 = addx2(ar1, rd[3]);
            ah0 = addx2(ah0, rd[4]); ah1 = addx2(ah1, rd[5]);

            float azc[2][2], arc[2][2], ahc[2][2];
            unpack2(az0, azc[0][0], azc[0][1]);
            unpack2(az1, azc[1][0], azc[1][1]);
            unpack2(ar0, arc[0][0], arc[0][1]);
            unpack2(ar1, arc[1][0], arc[1][1]);
            unpack2(ah0, ahc[0][0], ahc[0][1]);
            unpack2(ah1, ahc[1][0], ahc[1][1]);

            float hold[2][2] = {{ho0.x, ho1.x}, {ho0.y, ho1.y}};
            float bzv[2]  = {bz2.x, bz2.y};
            float brvv[2] = {br2.x, br2.y};
            float bhv[2]  = {bh2.x, bh2.y};
            float hnew[2][2];
#pragma unroll
            for (int rr = 0; rr < 2; ++rr) {
                float xzv[2] = {xzp[rr].x, xzp[rr].y};
                float xrv[2] = {xrp[rr].x, xrp[rr].y};
                float xhv[2] = {xhp[rr].x, xhp[rr].y};
#pragma unroll
                for (int cc = 0; cc < 2; ++cc) {
                    float z  = fsig(xzv[cc] + azc[rr][cc] + bzv[cc]);
                    float rg = fsig(xrv[cc] + arc[rr][cc] + brvv[cc]);
                    float hv = ftanh(xhv[cc] + rg * (ahc[rr][cc] + bhv[cc]));
                    hnew[rr][cc] = z * hold[rr][cc] + (1.0f - z) * hv;
                }
            }
            *(float2*)(hnx + (size_t)c0 * BB + r0)       = make_float2(hnew[0][0], hnew[1][0]);
            *(float2*)(hnx + (size_t)(c0 + 1) * BB + r0) = make_float2(hnew[0][1], hnew[1][1]);
        }

        // grid barrier
        __threadfence();
        __syncthreads();
        if (tid == 0) {
            atomicAdd(&g_bar, 1u);
            unsigned target = nCTA * (unsigned)(t + 1);
            while (*(volatile unsigned*)&g_bar < target) { }
            __threadfence();
        }
        __syncthreads();
    }
}

// ---------------- final: logits = h_last @ Wf + bf ---------------------------
__global__ void final_logits(const float* __restrict__ Wf,
                             const float* __restrict__ bf,
                             float* __restrict__ out) {
    int tid = threadIdx.x;          // 256 threads: r = tid>>1, c = tid&1
    int r = tid >> 1;
    int c = tid & 1;
    const float* h = g_hT[TT & 1];  // T even -> buffer 0, layout [k][r]
    float acc = 0.0f;
    for (int k = 0; k < HH; ++k)
        acc += h[(size_t)k * BB + r] * Wf[k * NCLS + c];
    out[r * NCLS + c] = acc + bf[c];
}

// ---------------- launch -----------------------------------------------------
extern "C" void kernel_launch(void* const* d_in, const int* in_sizes, int n_in,
                              void* d_out, int out_size) {
    const float* x   = (const float*)d_in[0];
    const float* W   = (const float*)d_in[1];
    const float* R   = (const float*)d_in[2];
    const float* b_i = (const float*)d_in[3];
    const float* b_r = (const float*)d_in[4];
    const float* Wf  = (const float*)d_in[5];
    const float* bf  = (const float*)d_in[6];
    float* out = (float*)d_out;

    float* xp;
    cudaGetSymbolAddress((void**)&xp, g_xp);

    static bool attr_set = false;
    if (!attr_set) {
        cudaFuncSetAttribute(gru_recurrent,
                             cudaFuncAttributeMaxDynamicSharedMemorySize, SMEM_DYN);
        attr_set = true;
    }

    init_kernel<<<(BB * HH + 255) / 256, 256>>>();
    build_Rp<<<(768 * 512 + 255) / 256, 256>>>(R);
    {
        dim3 grid(H3 / BN, (BB * TT) / BM);
        gemm_xw<<<grid, 256>>>(x, W, b_i, xp, BB * TT, H3, DD);
    }
    gru_recurrent<<<HH / 4, 256, SMEM_DYN>>>(xp, b_r);
    final_logits<<<1, 256>>>(Wf, bf, out);
}

// round 11
// speedup vs baseline: 1.3747x; 1.3401x over previous
#include <cuda_runtime.h>
#include <math.h>
#include <stdint.h>

// Problem dims (fixed)
#define BB   128
#define TT   1024
#define DD   512
#define HH   512
#define H3   1536
#define NCLS 2

typedef unsigned long long ull;

// v4 recurrence smem layout: 4 regions x (128 k x 64 rows) + R + reduce
#define REG_B   32768                      // 128k x 64 floats
#define HS_B    (4 * REG_B)                // 128KB
#define RS_OFF  HS_B
#define RS_B    (12 * 512 * 8)             // 48KB paired R (3 gates x 4 colpairs)
#define RED_OFF (RS_OFF + RS_B)
#define RED_B   (128 * 6 * 8)              // 6KB
#define SMEM_DYN (RED_OFF + RED_B)

// ---------------- scratch ----------------------------------------------------
__device__ float  g_xp[(size_t)BB * TT * H3];   // [B*T, 3H], row m = b*T + t
__device__ float2 g_Rp[768 * 512];              // paired Rt: g_Rp[i][k] = (R[k][2i], R[k][2i+1])
__device__ float  g_hT[2][HH * BB];             // hidden, TRANSPOSED [k][r]
__device__ unsigned int g_bar;

// ---------------- f32x2 helpers ---------------------------------------------
__device__ __forceinline__ ull pack2(float a, float b) {
    ull r; asm("mov.b64 %0, {%1, %2};" : "=l"(r) : "f"(a), "f"(b)); return r;
}
__device__ __forceinline__ void unpack2(ull p, float& a, float& b) {
    asm("mov.b64 {%0, %1}, %2;" : "=f"(a), "=f"(b) : "l"(p));
}
__device__ __forceinline__ ull ffma2(ull a, ull b, ull c) {
    ull d; asm("fma.rn.f32x2 %0, %1, %2, %3;" : "=l"(d) : "l"(a), "l"(b), "l"(c)); return d;
}
__device__ __forceinline__ ull addx2(ull a, ull b) {
    ull d; asm("add.rn.f32x2 %0, %1, %2;" : "=l"(d) : "l"(a), "l"(b)); return d;
}
__device__ __forceinline__ void cpa16(uint32_t s, const void* g) {
    asm volatile("cp.async.cg.shared.global [%0], [%1], 16;" :: "r"(s), "l"(g));
}
#define CP_COMMIT() asm volatile("cp.async.commit_group;")
#define CP_WAIT1()  asm volatile("cp.async.wait_group 1;")
#define CP_WAIT0()  asm volatile("cp.async.wait_group 0;")

// ---------------- init -------------------------------------------------------
__global__ void init_kernel() {
    int idx = blockIdx.x * blockDim.x + threadIdx.x;
    if (idx == 0) g_bar = 0u;
    if (idx < BB * HH) g_hT[0][idx] = 0.0f;
}

// ---------------- build paired R: R [H,3H] -> g_Rp [768][512] ----------------
__global__ void build_Rp(const float* __restrict__ R) {
    int idx = blockIdx.x * blockDim.x + threadIdx.x;  // over 768*512
    if (idx < 768 * 512) {
        int i = idx >> 9;        // pair index (0..767), cols 2i,2i+1
        int k = idx & 511;
        g_Rp[idx] = make_float2(R[(size_t)k * H3 + 2 * i], R[(size_t)k * H3 + 2 * i + 1]);
    }
}

// ---------------- GEMM1: xp = x @ W + b_i (f32x2) ----------------------------
#define BM 128
#define BN 128
#define BKK 8
#define TM 8
#define TN 8

__global__ void __launch_bounds__(256, 2)
gemm_xw(const float* __restrict__ A, const float* __restrict__ Bm,
        const float* __restrict__ bias, float* __restrict__ C,
        int M, int N, int K) {
    __shared__ float As[BKK][BM];
    __shared__ float Bs[BKK][BN];

    const int tid = threadIdx.x;
    const int brow = blockIdx.y;
    const int bcol = blockIdx.x;

    const int a_row = tid >> 1;
    const int a_col = (tid & 1) * 4;
    const int b_row = tid >> 5;
    const int b_col = (tid & 31) * 4;

    const int tx = tid & 15;
    const int ty = tid >> 4;

    ull accp[TM][TN / 2];
#pragma unroll
    for (int i = 0; i < TM; ++i)
#pragma unroll
        for (int j = 0; j < TN / 2; ++j) accp[i][j] = 0ull;

    const float* Ab = A + (size_t)(brow * BM) * K;
    const float* Bb = Bm + bcol * BN;

    for (int k0 = 0; k0 < K; k0 += BKK) {
        float4 av = *(const float4*)(Ab + (size_t)a_row * K + k0 + a_col);
        As[a_col + 0][a_row] = av.x;
        As[a_col + 1][a_row] = av.y;
        As[a_col + 2][a_row] = av.z;
        As[a_col + 3][a_row] = av.w;
        float4 bv = *(const float4*)(Bb + (size_t)(k0 + b_row) * N + b_col);
        *(float4*)&Bs[b_row][b_col] = bv;
        __syncthreads();

#pragma unroll
        for (int k = 0; k < BKK; ++k) {
            float ar[TM];
            float4 a0 = *(const float4*)&As[k][ty * TM];
            float4 a1 = *(const float4*)&As[k][ty * TM + 4];
            ar[0]=a0.x; ar[1]=a0.y; ar[2]=a0.z; ar[3]=a0.w;
            ar[4]=a1.x; ar[5]=a1.y; ar[6]=a1.z; ar[7]=a1.w;
            ulonglong2 bq0 = *(const ulonglong2*)&Bs[k][tx * TN];
            ulonglong2 bq1 = *(const ulonglong2*)&Bs[k][tx * TN + 4];
            ull bp0 = bq0.x, bp1 = bq0.y, bp2 = bq1.x, bp3 = bq1.y;
#pragma unroll
            for (int i = 0; i < TM; ++i) {
                ull as = pack2(ar[i], ar[i]);
                accp[i][0] = ffma2(as, bp0, accp[i][0]);
                accp[i][1] = ffma2(as, bp1, accp[i][1]);
                accp[i][2] = ffma2(as, bp2, accp[i][2]);
                accp[i][3] = ffma2(as, bp3, accp[i][3]);
            }
        }
        __syncthreads();
    }

    const int c_col0 = bcol * BN + tx * TN;
    float bsv[TN];
#pragma unroll
    for (int j = 0; j < TN; ++j) bsv[j] = bias[c_col0 + j];

    float* Cb = C + (size_t)(brow * BM + ty * TM) * N + c_col0;
#pragma unroll
    for (int i = 0; i < TM; ++i) {
#pragma unroll
        for (int j = 0; j < TN / 2; ++j) {
            float lo, hi; unpack2(accp[i][j], lo, hi);
            Cb[(size_t)i * N + 2 * j]     = lo + bsv[2 * j];
            Cb[(size_t)i * N + 2 * j + 1] = hi + bsv[2 * j + 1];
        }
    }
}

// ---------------- persistent GRU recurrence (v4: batch-split) ----------------
// 128 CTAs = 64 col-groups (8 cols) x 2 batch halves (64 rows).
// 256 threads: half = tid>>7 reduces k in [half*256, half*256+256);
//   lt = tid&127: cpi = lt>>5 (colpair 0..3), rp = lt&31 (local rows 2rp,2rp+1).
// Each CTA stages ONLY its 64 batch rows: 512k x 64r = 128KB, in 2 commit
// groups (regions 0+1 then 2+3), single-buffered -> 2 waits/step.
// region = part*2 + half holds k in [half*256 + part*128, +128).

__device__ __forceinline__ float fsig(float x)  { return 1.0f / (1.0f + __expf(-x)); }
__device__ __forceinline__ float ftanh(float x) { return 1.0f - 2.0f / (__expf(2.0f * x) + 1.0f); }

// stage one part: region part*2 (k half0) + region part*2+1 (k half1); one commit
__device__ __forceinline__ void stage_part(uint32_t hsS, const float* hcur,
                                           int part, int bh, int tid) {
    int kA = (tid >> 1) + part * 128;          // k for half0 region
    int seg = tid & 1;                          // 32-row segment
    // region part*2: k = kA (in [part*128, part*128+128))
    {
        uint32_t dst = hsS + (uint32_t)((part * 2) * REG_B) + (uint32_t)(((kA - part * 128) << 8) + (seg << 7));
        const char* src = (const char*)hcur + (size_t)kA * 512 + bh * 256 + seg * 128;
#pragma unroll
        for (int j = 0; j < 8; ++j) cpa16(dst + j * 16, src + j * 16);
    }
    // region part*2+1: k = kA + 256
    {
        uint32_t dst = hsS + (uint32_t)((part * 2 + 1) * REG_B) + (uint32_t)(((kA - part * 128) << 8) + (seg << 7));
        const char* src = (const char*)hcur + (size_t)(kA + 256) * 512 + bh * 256 + seg * 128;
#pragma unroll
        for (int j = 0; j < 8; ++j) cpa16(dst + j * 16, src + j * 16);
    }
    CP_COMMIT();
}

__global__ void __launch_bounds__(256, 1)
gru_recurrent(const float* __restrict__ xp, const float* __restrict__ brv) {
    extern __shared__ char sm[];
    float*  hs  = (float*)sm;
    float2* Rs  = (float2*)(sm + RS_OFF);
    ull*    red = (ull*)(sm + RED_OFF);

    const int tid  = threadIdx.x;
    const int half = tid >> 7;
    const int lt   = tid & 127;
    const int cpi  = lt >> 5;          // 0..3 (colpair within 8 cols)
    const int rp   = lt & 31;          // 0..31 (local row pair)
    const int r0l  = rp * 2;           // local row 0..62
    const int blk  = blockIdx.x;
    const int cg   = blk >> 1;         // col-group 0..63
    const int bh   = blk & 1;          // batch half
    const int c0   = cg * 8 + 2 * cpi;
    const int gr0  = bh * 64 + r0l;    // global row

    // persistent paired R: 12 pair-rows (gate*4 + cpi) x 512 k
    for (int i = tid; i < 12 * 512; i += 256) {
        int L = i >> 9;
        int k = i & 511;
        int gate = L >> 2, cp = L & 3;
        int gp = gate * 256 + cg * 4 + cp;
        Rs[(size_t)L * 512 + k] = g_Rp[(size_t)gp * 512 + k];
    }

    const float2 bz2 = *(const float2*)(brv + c0);
    const float2 br2 = *(const float2*)(brv + HH + c0);
    const float2 bh2 = *(const float2*)(brv + 2 * HH + c0);

    const unsigned nCTA = gridDim.x;
    uint32_t hsS = (uint32_t)__cvta_generic_to_shared(hs);
    __syncthreads();

    for (int t = 0; t < TT; ++t) {
        const float* hcur = g_hT[t & 1];
        float* hnx = g_hT[(t + 1) & 1];

        // prefetch xp gate inputs + h_old from global (latency overlaps staging)
        float2 xzp[2], xrp[2], xhp[2];
        float2 ho0, ho1;
#pragma unroll
        for (int rr = 0; rr < 2; ++rr) {
            const float* xb = xp + ((size_t)(gr0 + rr) * TT + t) * H3;
            xzp[rr] = *(const float2*)(xb + c0);
            xrp[rr] = *(const float2*)(xb + HH + c0);
            xhp[rr] = *(const float2*)(xb + 2 * HH + c0);
        }
        ho0 = *(const float2*)(hcur + (size_t)c0 * BB + gr0);        // col c0
        ho1 = *(const float2*)(hcur + (size_t)(c0 + 1) * BB + gr0);  // col c0+1

        // stage both parts up-front (disjoint regions, single-buffered)
        stage_part(hsS, hcur, 0, bh, tid);
        stage_part(hsS, hcur, 1, bh, tid);

        ull az0 = 0, az1 = 0, ar0 = 0, ar1 = 0, ah0 = 0, ah1 = 0;

#pragma unroll
        for (int p = 0; p < 2; ++p) {
            if (p == 0) { CP_WAIT1(); } else { CP_WAIT0(); }
            __syncthreads();

            const float* hb = hs + (size_t)((p * 2 + half) * (REG_B / 4));
            const int kg = half * 256 + p * 128;
            const float2* Rz = Rs + (size_t)(0 + cpi) * 512 + kg;
            const float2* Rr = Rs + (size_t)(4 + cpi) * 512 + kg;
            const float2* Rh = Rs + (size_t)(8 + cpi) * 512 + kg;

#pragma unroll 8
            for (int kk = 0; kk < 128; kk += 2) {
                ull hp0 = *(const ull*)(hb + (size_t)kk * 64 + r0l);
                ull hp1 = *(const ull*)(hb + (size_t)(kk + 1) * 64 + r0l);
                float h00, h01; unpack2(hp0, h00, h01);
                float h10, h11; unpack2(hp1, h10, h11);
                ull s00 = pack2(h00, h00), s01 = pack2(h01, h01);
                ull s10 = pack2(h10, h10), s11 = pack2(h11, h11);

                ulonglong2 vz = *(const ulonglong2*)(Rz + kk);
                ulonglong2 vr = *(const ulonglong2*)(Rr + kk);
                ulonglong2 vh = *(const ulonglong2*)(Rh + kk);

                az0 = ffma2(s00, vz.x, az0);  az1 = ffma2(s01, vz.x, az1);
                ar0 = ffma2(s00, vr.x, ar0);  ar1 = ffma2(s01, vr.x, ar1);
                ah0 = ffma2(s00, vh.x, ah0);  ah1 = ffma2(s01, vh.x, ah1);
                az0 = ffma2(s10, vz.y, az0);  az1 = ffma2(s11, vz.y, az1);
                ar0 = ffma2(s10, vr.y, ar0);  ar1 = ffma2(s11, vr.y, ar1);
                ah0 = ffma2(s10, vh.y, ah0);  ah1 = ffma2(s11, vh.y, ah1);
            }
        }

        // K-split reduction: half 1 -> smem, half 0 accumulates
        if (half) {
            ull* rd = red + (size_t)lt * 6;
            rd[0] = az0; rd[1] = az1; rd[2] = ar0;
            rd[3] = ar1; rd[4] = ah0; rd[5] = ah1;
        }
        __syncthreads();
        if (!half) {
            const ull* rd = red + (size_t)lt * 6;
            az0 = addx2(az0, rd[0]); az1 = addx2(az1, rd[1]);
            ar0 = addx2(ar0, rd[2]); ar1 = addx2(ar1, rd[3]);
            ah0 = addx2(ah0, rd[4]); ah1 = addx2(ah1, rd[5]);

            float azc[2][2], arc[2][2], ahc[2][2];
            unpack2(az0, azc[0][0], azc[0][1]);
            unpack2(az1, azc[1][0], azc[1][1]);
            unpack2(ar0, arc[0][0], arc[0][1]);
            unpack2(ar1, arc[1][0], arc[1][1]);
            unpack2(ah0, ahc[0][0], ahc[0][1]);
            unpack2(ah1, ahc[1][0], ahc[1][1]);

            float hold[2][2] = {{ho0.x, ho1.x}, {ho0.y, ho1.y}};
            float bzv[2]  = {bz2.x, bz2.y};
            float brvv[2] = {br2.x, br2.y};
            float bhv[2]  = {bh2.x, bh2.y};
            float hnew[2][2];
#pragma unroll
            for (int rr = 0; rr < 2; ++rr) {
                float xzv[2] = {xzp[rr].x, xzp[rr].y};
                float xrv[2] = {xrp[rr].x, xrp[rr].y};
                float xhv[2] = {xhp[rr].x, xhp[rr].y};
#pragma unroll
                for (int cc = 0; cc < 2; ++cc) {
                    float z  = fsig(xzv[cc] + azc[rr][cc] + bzv[cc]);
                    float rg = fsig(xrv[cc] + arc[rr][cc] + brvv[cc]);
                    float hv = ftanh(xhv[cc] + rg * (ahc[rr][cc] + bhv[cc]));
                    hnew[rr][cc] = z * hold[rr][cc] + (1.0f - z) * hv;
                }
            }
            *(float2*)(hnx + (size_t)c0 * BB + gr0)       = make_float2(hnew[0][0], hnew[1][0]);
            *(float2*)(hnx + (size_t)(c0 + 1) * BB + gr0) = make_float2(hnew[0][1], hnew[1][1]);

            __threadfence();   // only storing threads need the release
        }

        // grid barrier
        __syncthreads();
        if (tid == 0) {
            atomicAdd(&g_bar, 1u);
            unsigned target = nCTA * (unsigned)(t + 1);
            while (*(volatile unsigned*)&g_bar < target) { }
            __threadfence();
        }
        __syncthreads();
    }
}

// ---------------- final: logits = h_last @ Wf + bf ---------------------------
__global__ void final_logits(const float* __restrict__ Wf,
                             const float* __restrict__ bf,
                             float* __restrict__ out) {
    int tid = threadIdx.x;          // 256 threads: r = tid>>1, c = tid&1
    int r = tid >> 1;
    int c = tid & 1;
    const float* h = g_hT[TT & 1];  // T even -> buffer 0, layout [k][r]
    float acc = 0.0f;
    for (int k = 0; k < HH; ++k)
        acc += h[(size_t)k * BB + r] * Wf[k * NCLS + c];
    out[r * NCLS + c] = acc + bf[c];
}

// ---------------- launch -----------------------------------------------------
extern "C" void kernel_launch(void* const* d_in, const int* in_sizes, int n_in,
                              void* d_out, int out_size) {
    const float* x   = (const float*)d_in[0];
    const float* W   = (const float*)d_in[1];
    const float* R   = (const float*)d_in[2];
    const float* b_i = (const float*)d_in[3];
    const float* b_r = (const float*)d_in[4];
    const float* Wf  = (const float*)d_in[5];
    const float* bf  = (const float*)d_in[6];
    float* out = (float*)d_out;

    float* xp;
    cudaGetSymbolAddress((void**)&xp, g_xp);

    static bool attr_set = false;
    if (!attr_set) {
        cudaFuncSetAttribute(gru_recurrent,
                             cudaFuncAttributeMaxDynamicSharedMemorySize, SMEM_DYN);
        attr_set = true;
    }

    init_kernel<<<(BB * HH + 255) / 256, 256>>>();
    build_Rp<<<(768 * 512 + 255) / 256, 256>>>(R);
    {
        dim3 grid(H3 / BN, (BB * TT) / BM);
        gemm_xw<<<grid, 256>>>(x, W, b_i, xp, BB * TT, H3, DD);
    }
    gru_recurrent<<<128, 256, SMEM_DYN>>>(xp, b_r);
    final_logits<<<1, 256>>>(Wf, bf, out);
}